// round 6
// baseline (speedup 1.0000x reference)
#include <cuda_runtime.h>
#include <math.h>
#include <stdint.h>

// Problem constants
#define N_IMG     16
#define N_CH      3
#define NSLICE    (N_IMG * N_CH)          // 48
#define BINS      64
#define SLICE_ELEMS (1024 * 1024)

#define HTHREADS  256
#define BPS       9                               // blocks per slice -> 432 blocks
#define NBLOCKS   (NSLICE * BPS)
#define HSMEM_BYTES (BINS * HTHREADS * 4)         // [64][256] uint32 = 64 KB

// Params layout (in_ch,out_ch row-major), per reference
#define P_W1 0
#define P_B1 24576
#define P_W2 24704
#define P_B2 28800
#define P_G  28832

__device__ float g_part[NBLOCKS * BINS];
__device__ unsigned int g_ctr;   // zero-initialized; finisher resets to 0 each call

__global__ __launch_bounds__(HTHREADS, 3)
void fused_kernel(const float* __restrict__ img,
                  const float* __restrict__ params,
                  float* __restrict__ out) {
    extern __shared__ unsigned int hh[];   // [BINS][HTHREADS]: lo half +1, hi half +65536
    const int tid = threadIdx.x;

    #pragma unroll
    for (int i = tid; i < BINS * HTHREADS; i += HTHREADS) hh[i] = 0u;
    __syncthreads();

    const int slice = blockIdx.x / BPS;
    const int chunk = blockIdx.x % BPS;
    const float4* base = reinterpret_cast<const float4*>(img + (size_t)slice * SLICE_ELEMS);
    const int n4   = SLICE_ELEMS / 4;                 // 262144
    const int per  = (n4 + BPS - 1) / BPS;            // 29128
    const int start = chunk * per;
    const int end   = min(start + per, n4);

    unsigned int* h = hh + tid;   // word index bin*256 + tid -> bank = tid%32, conflict-free

#define PROC(v4) { \
        int b0 = min((int)((v4).x * 64.0f), 63); \
        int b1 = min((int)((v4).y * 64.0f), 63); \
        int b2 = min((int)((v4).z * 64.0f), 63); \
        int b3 = min((int)((v4).w * 64.0f), 63); \
        h[b0 * HTHREADS] += 1u; \
        h[b1 * HTHREADS] += 65536u; \
        h[b2 * HTHREADS] += 1u; \
        h[b3 * HTHREADS] += 65536u; }

    int i = start + tid;
    for (; i + 7 * HTHREADS < end; i += 8 * HTHREADS) {
        float4 v0 = __ldcs(base + i);
        float4 v1 = __ldcs(base + i + 1 * HTHREADS);
        float4 v2 = __ldcs(base + i + 2 * HTHREADS);
        float4 v3 = __ldcs(base + i + 3 * HTHREADS);
        float4 v4 = __ldcs(base + i + 4 * HTHREADS);
        float4 v5 = __ldcs(base + i + 5 * HTHREADS);
        float4 v6 = __ldcs(base + i + 6 * HTHREADS);
        float4 v7 = __ldcs(base + i + 7 * HTHREADS);
        PROC(v0); PROC(v1); PROC(v2); PROC(v3);
        PROC(v4); PROC(v5); PROC(v6); PROC(v7);
    }
    for (; i < end; i += HTHREADS) {
        float4 a = __ldcs(base + i);
        PROC(a);
    }
#undef PROC
    __syncthreads();

    // Warp-shuffle epilogue: warp w reduces bins 8w..8w+7.
    const int wid  = tid >> 5;
    const int lane = tid & 31;
    #pragma unroll
    for (int r = 0; r < 8; r++) {
        const int b = wid * 8 + r;
        const unsigned int* row = hh + b * HTHREADS;
        unsigned int s = row[lane] + row[lane + 32] + row[lane + 64] + row[lane + 96]
                       + row[lane + 128] + row[lane + 160] + row[lane + 192] + row[lane + 224];
        #pragma unroll
        for (int d = 16; d >= 1; d >>= 1)
            s += __shfl_down_sync(0xFFFFFFFFu, s, d);
        if (lane == 0)
            g_part[blockIdx.x * BINS + b] = (float)((s & 0xFFFFu) + (s >> 16));
    }

    // ---- Completion protocol: last block to arrive runs the MLP ----
    __threadfence();
    __shared__ int s_fin;
    if (tid == 0) {
        unsigned int old = atomicAdd(&g_ctr, 1u);
        s_fin = (old == NBLOCKS - 1) ? 1 : 0;
        if (s_fin) g_ctr = 0;   // all adds done; safe deterministic reset
    }
    __syncthreads();
    if (!s_fin) return;
    __threadfence();   // acquire: make all g_part stores visible to our reads

    // ---- MLP in the finisher block (reuse smem as float) ----
    float* s = reinterpret_cast<float*>(hh);
    float* s_hist = s;          // [16][192]
    float* s_h1   = s + 3072;   // [16][128]

    // Gather + reduce per-chunk partials: s_hist[n][c*64+b]
    #pragma unroll
    for (int i2 = tid; i2 < 3072; i2 += HTHREADS) {
        int n   = i2 / 192;
        int col = i2 - n * 192;
        int c   = col >> 6;
        int b   = col & 63;
        const float* p = g_part + ((n * 3 + c) * BPS) * BINS + b;
        float acc = 0.0f;
        #pragma unroll
        for (int k = 0; k < BPS; k++) acc += p[k * BINS];
        s_hist[i2] = acc;
    }
    __syncthreads();

    // Layer 1: j = tid&127, half = tid>>7 -> images n0..n0+7
    {
        const int j  = tid & 127;
        const int n0 = (tid >> 7) * 8;
        float a0 = 0, a1 = 0, a2 = 0, a3 = 0, a4 = 0, a5 = 0, a6 = 0, a7 = 0;
        const float* hb = s_hist + n0 * 192;
        #pragma unroll 4
        for (int c = 0; c < 192; c++) {
            float w = __ldg(params + P_W1 + c * 128 + j);
            a0 = fmaf(hb[c], w, a0);
            a1 = fmaf(hb[192 + c], w, a1);
            a2 = fmaf(hb[384 + c], w, a2);
            a3 = fmaf(hb[576 + c], w, a3);
            a4 = fmaf(hb[768 + c], w, a4);
            a5 = fmaf(hb[960 + c], w, a5);
            a6 = fmaf(hb[1152 + c], w, a6);
            a7 = fmaf(hb[1344 + c], w, a7);
        }
        float bj = __ldg(params + P_B1 + j);
        s_h1[(n0 + 0) * 128 + j] = fmaxf(a0 + bj, 0.0f);
        s_h1[(n0 + 1) * 128 + j] = fmaxf(a1 + bj, 0.0f);
        s_h1[(n0 + 2) * 128 + j] = fmaxf(a2 + bj, 0.0f);
        s_h1[(n0 + 3) * 128 + j] = fmaxf(a3 + bj, 0.0f);
        s_h1[(n0 + 4) * 128 + j] = fmaxf(a4 + bj, 0.0f);
        s_h1[(n0 + 5) * 128 + j] = fmaxf(a5 + bj, 0.0f);
        s_h1[(n0 + 6) * 128 + j] = fmaxf(a6 + bj, 0.0f);
        s_h1[(n0 + 7) * 128 + j] = fmaxf(a7 + bj, 0.0f);
    }
    __syncthreads();

    // Layer 2 + sigmoid: thread t -> k = t&31, images q and q+8 (q = t>>5)
    {
        const int k = tid & 31;
        const int q = tid >> 5;
        float acc0 = 0.0f, acc1 = 0.0f;
        const float* h0 = s_h1 + q * 128;
        const float* h1p = s_h1 + (q + 8) * 128;
        #pragma unroll 8
        for (int c = 0; c < 128; c++) {
            float w = __ldg(params + P_W2 + c * 32 + k);
            acc0 = fmaf(h0[c],  w, acc0);
            acc1 = fmaf(h1p[c], w, acc1);
        }
        float bias = __ldg(params + P_B2 + k) + __ldg(params + P_G);
        out[q * 32 + k]       = 1.0f / (1.0f + expf(-(acc0 + bias)));
        out[(q + 8) * 32 + k] = 1.0f / (1.0f + expf(-(acc1 + bias)));
    }
}

extern "C" void kernel_launch(void* const* d_in, const int* in_sizes, int n_in,
                              void* d_out, int out_size) {
    const float* img    = (const float*)d_in[0];
    const float* params = (const float*)d_in[1];
    float* out          = (float*)d_out;

    static bool attr_set = false;
    if (!attr_set) {
        cudaFuncSetAttribute(fused_kernel, cudaFuncAttributeMaxDynamicSharedMemorySize, HSMEM_BYTES);
        attr_set = true;
    }

    fused_kernel<<<NBLOCKS, HTHREADS, HSMEM_BYTES>>>(img, params, out);
}

// round 7
// speedup vs baseline: 1.2527x; 1.2527x over previous
#include <cuda_runtime.h>
#include <math.h>
#include <stdint.h>

// Problem constants
#define N_IMG     16
#define N_CH      3
#define NSLICE    (N_IMG * N_CH)          // 48
#define BINS      64
#define SLICE_ELEMS (1024 * 1024)

#define HTHREADS  256
#define BPS       9                               // blocks per slice -> 432 blocks
#define NBLOCKS   (NSLICE * BPS)
#define HSMEM_BYTES (BINS * HTHREADS * 4)         // [64][256] uint32 = 64 KB

// Params layout (in_ch,out_ch row-major), per reference
#define P_W1 0
#define P_B1 24576
#define P_W2 24704
#define P_B2 28800
#define P_G  28832

__device__ float g_part[NBLOCKS * BINS];

__global__ __launch_bounds__(HTHREADS, 2)
void hist_kernel(const float* __restrict__ img) {
    extern __shared__ unsigned int hh[];   // [BINS][HTHREADS]: lo half +1, hi half +65536
    const int tid = threadIdx.x;

    #pragma unroll
    for (int i = tid; i < BINS * HTHREADS; i += HTHREADS) hh[i] = 0u;
    __syncthreads();

    const int slice = blockIdx.x / BPS;
    const int chunk = blockIdx.x % BPS;
    const float4* base = reinterpret_cast<const float4*>(img + (size_t)slice * SLICE_ELEMS);
    const int n4   = SLICE_ELEMS / 4;                 // 262144
    const int per  = (n4 + BPS - 1) / BPS;            // 29128
    const int start = chunk * per;
    const int end   = min(start + per, n4);

    unsigned int* h = hh + tid;   // word index bin*256 + tid -> bank = tid%32, conflict-free

#define PROC(v4) { \
        int b0 = min((int)((v4).x * 64.0f), 63); \
        int b1 = min((int)((v4).y * 64.0f), 63); \
        int b2 = min((int)((v4).z * 64.0f), 63); \
        int b3 = min((int)((v4).w * 64.0f), 63); \
        h[b0 * HTHREADS] += 1u; \
        h[b1 * HTHREADS] += 65536u; \
        h[b2 * HTHREADS] += 1u; \
        h[b3 * HTHREADS] += 65536u; }

    // Double-buffered: prefetch next 8 LDG.128 BEFORE processing current 8,
    // so loads stay in flight during the serialized smem RMW chain.
    int i = start + tid;
    float4 A[8], B[8];
    bool hasA = (i + 7 * HTHREADS < end);
    if (hasA) {
        #pragma unroll
        for (int u = 0; u < 8; u++) A[u] = __ldcs(base + i + u * HTHREADS);
    }
    while (hasA) {
        const int j = i + 8 * HTHREADS;
        const bool hasB = (j + 7 * HTHREADS < end);
        if (hasB) {
            #pragma unroll
            for (int u = 0; u < 8; u++) B[u] = __ldcs(base + j + u * HTHREADS);
        }
        #pragma unroll
        for (int u = 0; u < 8; u++) PROC(A[u]);
        i = j;
        if (!hasB) break;
        const int k = j + 8 * HTHREADS;
        hasA = (k + 7 * HTHREADS < end);
        if (hasA) {
            #pragma unroll
            for (int u = 0; u < 8; u++) A[u] = __ldcs(base + k + u * HTHREADS);
        }
        #pragma unroll
        for (int u = 0; u < 8; u++) PROC(B[u]);
        i = k;
    }
    for (; i < end; i += HTHREADS) {
        float4 a = __ldcs(base + i);
        PROC(a);
    }
#undef PROC
    __syncthreads();

    // Warp-shuffle epilogue: warp w reduces bins 8w..8w+7.
    const int wid  = tid >> 5;
    const int lane = tid & 31;
    #pragma unroll
    for (int r = 0; r < 8; r++) {
        const int b = wid * 8 + r;
        const unsigned int* row = hh + b * HTHREADS;
        unsigned int s = row[lane] + row[lane + 32] + row[lane + 64] + row[lane + 96]
                       + row[lane + 128] + row[lane + 160] + row[lane + 192] + row[lane + 224];
        #pragma unroll
        for (int d = 16; d >= 1; d >>= 1)
            s += __shfl_down_sync(0xFFFFFFFFu, s, d);
        if (lane == 0)
            g_part[blockIdx.x * BINS + b] = (float)((s & 0xFFFFu) + (s >> 16));
    }
}

// MLP with PDL: grid=16 (one image per block), 256 threads.
#define MLP_BLOCKS  16
#define MLP_THREADS 256
#define MLP_SMEM_FLOATS (24576 + 4096 + 192 + 256 + 128 + 128)
#define MLP_SMEM_BYTES  (MLP_SMEM_FLOATS * 4)

__global__ __launch_bounds__(MLP_THREADS, 1)
void mlp_kernel(const float* __restrict__ params, float* __restrict__ out) {
    extern __shared__ float smem[];
    float* s_w1   = smem;                 // [192][128]
    float* s_w2   = s_w1 + 24576;         // [128][32]
    float* s_hist = s_w2 + 4096;          // [192]
    float* s_p1   = s_hist + 192;         // [2][128] layer-1 partials
    float* s_h1   = s_p1 + 256;           // [128]
    float* s_l2   = s_h1 + 128;           // [4][32] layer-2 partials

    const int tid = threadIdx.x;
    const int n   = blockIdx.x;

    // ---- Pre-sync: stage weights (overlaps with hist via PDL) ----
    #pragma unroll
    for (int i = tid; i < 24576 / 4; i += MLP_THREADS)
        reinterpret_cast<float4*>(s_w1)[i] = reinterpret_cast<const float4*>(params + P_W1)[i];
    #pragma unroll
    for (int i = tid; i < 4096 / 4; i += MLP_THREADS)
        reinterpret_cast<float4*>(s_w2)[i] = reinterpret_cast<const float4*>(params + P_W2)[i];

    cudaGridDependencySynchronize();

    if (tid < 192) {
        int c = tid >> 6;
        int b = tid & 63;
        const float* p = g_part + ((n * 3 + c) * BPS) * BINS + b;
        float s = 0.0f;
        #pragma unroll
        for (int k = 0; k < BPS; k++) s += p[k * BINS];
        s_hist[tid] = s;
    }
    __syncthreads();

    // Layer 1: j = tid&127, half = tid>>7 covers c in [half*96, half*96+96)
    {
        const int j    = tid & 127;
        const int half = tid >> 7;
        const int c0   = half * 96;
        float acc = 0.0f;
        #pragma unroll 16
        for (int c = c0; c < c0 + 96; c++)
            acc = fmaf(s_hist[c], s_w1[c * 128 + j], acc);
        s_p1[half * 128 + j] = acc;
    }
    __syncthreads();
    if (tid < 128)
        s_h1[tid] = fmaxf(s_p1[tid] + s_p1[128 + tid] + params[P_B1 + tid], 0.0f);
    __syncthreads();

    if (tid < 128) {
        const int q = tid >> 5;
        const int k = tid & 31;
        float a = 0.0f;
        #pragma unroll
        for (int c = q * 32; c < q * 32 + 32; c++)
            a = fmaf(s_h1[c], s_w2[c * 32 + k], a);
        s_l2[tid] = a;
    }
    __syncthreads();

    if (tid < 32) {
        float a = params[P_B2 + tid] + params[P_G]
                + s_l2[tid] + s_l2[32 + tid] + s_l2[64 + tid] + s_l2[96 + tid];
        out[n * 32 + tid] = 1.0f / (1.0f + expf(-a));
    }
}

extern "C" void kernel_launch(void* const* d_in, const int* in_sizes, int n_in,
                              void* d_out, int out_size) {
    const float* img    = (const float*)d_in[0];
    const float* params = (const float*)d_in[1];
    float* out          = (float*)d_out;

    static bool attr_set = false;
    if (!attr_set) {
        cudaFuncSetAttribute(hist_kernel, cudaFuncAttributeMaxDynamicSharedMemorySize, HSMEM_BYTES);
        cudaFuncSetAttribute(mlp_kernel,  cudaFuncAttributeMaxDynamicSharedMemorySize, MLP_SMEM_BYTES);
        attr_set = true;
    }

    hist_kernel<<<NBLOCKS, HTHREADS, HSMEM_BYTES>>>(img);

    cudaLaunchConfig_t cfg = {};
    cfg.gridDim  = dim3(MLP_BLOCKS, 1, 1);
    cfg.blockDim = dim3(MLP_THREADS, 1, 1);
    cfg.dynamicSmemBytes = MLP_SMEM_BYTES;
    cudaLaunchAttribute attrs[1];
    attrs[0].id = cudaLaunchAttributeProgrammaticStreamSerialization;
    attrs[0].val.programmaticStreamSerializationAllowed = 1;
    cfg.attrs = attrs;
    cfg.numAttrs = 1;
    cudaLaunchKernelEx(&cfg, mlp_kernel, params, out);
}

// round 8
// speedup vs baseline: 1.3879x; 1.1079x over previous
#include <cuda_runtime.h>
#include <math.h>
#include <stdint.h>

// Problem constants
#define N_IMG     16
#define N_CH      3
#define NSLICE    (N_IMG * N_CH)          // 48
#define BINS      64
#define SLICE_ELEMS (1024 * 1024)

#define HTHREADS  128
#define BPS       9                               // blocks per slice -> 432 blocks (one wave at occ 3)
#define NBLOCKS   (NSLICE * BPS)
// Two u32 counter arrays [64][128] = 32 KB each
#define HSMEM_WORDS (2 * BINS * HTHREADS)
#define HSMEM_BYTES (HSMEM_WORDS * 4)             // 64 KB

// Params layout (in_ch,out_ch row-major), per reference
#define P_W1 0
#define P_B1 24576
#define P_W2 24704
#define P_B2 28800
#define P_G  28832

__device__ float g_part[NBLOCKS * BINS];

__global__ __launch_bounds__(HTHREADS, 3)
void hist_kernel(const float* __restrict__ img) {
    extern __shared__ unsigned int hh[];   // A = hh[0..8191], B = hh[8192..16383]
    const int tid = threadIdx.x;

    // zero both arrays (uint4 stores)
    {
        uint4* z = reinterpret_cast<uint4*>(hh);
        #pragma unroll
        for (int i = tid; i < HSMEM_WORDS / 4; i += HTHREADS)
            z[i] = make_uint4(0u, 0u, 0u, 0u);
    }
    __syncthreads();

    const int slice = blockIdx.x / BPS;
    const int chunk = blockIdx.x % BPS;
    const float4* base = reinterpret_cast<const float4*>(img + (size_t)slice * SLICE_ELEMS);
    const int n4   = SLICE_ELEMS / 4;                 // 262144
    const int per  = (n4 + BPS - 1) / BPS;            // 29128
    const int start = chunk * per;
    const int end   = min(start + per, n4);

    unsigned int* pA = hh + tid;                       // A[b][tid] at pA[b*128]
    unsigned int* pB = hh + BINS * HTHREADS + tid;     // B[b][tid] at pB[b*128]

    // Two independent RMW chains per pair: LDS_A,LDS_B overlap their 29-cyc latencies.
    // __fmul_rd guarantees bin <= 63 for v in [0,1) -- no clamp needed.
#define PROCPAIR(vA, vB) { \
        int ba = (int)__fmul_rd((vA), 64.0f); \
        int bb = (int)__fmul_rd((vB), 64.0f); \
        unsigned int ca = pA[ba * HTHREADS]; \
        unsigned int cb = pB[bb * HTHREADS]; \
        pA[ba * HTHREADS] = ca + 1u; \
        pB[bb * HTHREADS] = cb + 1u; }
#define PROC(v4) { PROCPAIR((v4).x, (v4).y); PROCPAIR((v4).z, (v4).w); }

    // Double-buffered: prefetch next 8 LDG.128 before processing current 8.
    int i = start + tid;
    float4 A[8], B[8];
    bool hasA = (i + 7 * HTHREADS < end);
    if (hasA) {
        #pragma unroll
        for (int u = 0; u < 8; u++) A[u] = __ldcs(base + i + u * HTHREADS);
    }
    while (hasA) {
        const int j = i + 8 * HTHREADS;
        const bool hasB = (j + 7 * HTHREADS < end);
        if (hasB) {
            #pragma unroll
            for (int u = 0; u < 8; u++) B[u] = __ldcs(base + j + u * HTHREADS);
        }
        #pragma unroll
        for (int u = 0; u < 8; u++) PROC(A[u]);
        i = j;
        if (!hasB) break;
        const int k = j + 8 * HTHREADS;
        hasA = (k + 7 * HTHREADS < end);
        if (hasA) {
            #pragma unroll
            for (int u = 0; u < 8; u++) A[u] = __ldcs(base + k + u * HTHREADS);
        }
        #pragma unroll
        for (int u = 0; u < 8; u++) PROC(B[u]);
        i = k;
    }
    for (; i < end; i += HTHREADS) {
        float4 a = __ldcs(base + i);
        PROC(a);
    }
#undef PROC
#undef PROCPAIR
    __syncthreads();

    // Epilogue: warp w (of 4) reduces bins 16w..16w+15 over 128 columns x 2 arrays.
    const int wid  = tid >> 5;
    const int lane = tid & 31;
    #pragma unroll
    for (int r = 0; r < 16; r++) {
        const int b = wid * 16 + r;
        const unsigned int* ra = hh + b * HTHREADS;
        const unsigned int* rb = hh + BINS * HTHREADS + b * HTHREADS;
        unsigned int s = ra[lane] + ra[lane + 32] + ra[lane + 64] + ra[lane + 96]
                       + rb[lane] + rb[lane + 32] + rb[lane + 64] + rb[lane + 96];
        #pragma unroll
        for (int d = 16; d >= 1; d >>= 1)
            s += __shfl_down_sync(0xFFFFFFFFu, s, d);
        if (lane == 0)
            g_part[blockIdx.x * BINS + b] = (float)s;
    }
}

// MLP with PDL: grid=16 (one image per block), 256 threads.
#define MLP_BLOCKS  16
#define MLP_THREADS 256
#define MLP_SMEM_FLOATS (24576 + 4096 + 192 + 256 + 128 + 128)
#define MLP_SMEM_BYTES  (MLP_SMEM_FLOATS * 4)

__global__ __launch_bounds__(MLP_THREADS, 1)
void mlp_kernel(const float* __restrict__ params, float* __restrict__ out) {
    extern __shared__ float smem[];
    float* s_w1   = smem;                 // [192][128]
    float* s_w2   = s_w1 + 24576;         // [128][32]
    float* s_hist = s_w2 + 4096;          // [192]
    float* s_p1   = s_hist + 192;         // [2][128]
    float* s_h1   = s_p1 + 256;           // [128]
    float* s_l2   = s_h1 + 128;           // [4][32]

    const int tid = threadIdx.x;
    const int n   = blockIdx.x;

    // Pre-sync: stage weights (overlaps with hist via PDL)
    #pragma unroll
    for (int i = tid; i < 24576 / 4; i += MLP_THREADS)
        reinterpret_cast<float4*>(s_w1)[i] = reinterpret_cast<const float4*>(params + P_W1)[i];
    #pragma unroll
    for (int i = tid; i < 4096 / 4; i += MLP_THREADS)
        reinterpret_cast<float4*>(s_w2)[i] = reinterpret_cast<const float4*>(params + P_W2)[i];

    cudaGridDependencySynchronize();

    if (tid < 192) {
        int c = tid >> 6;
        int b = tid & 63;
        const float* p = g_part + ((n * 3 + c) * BPS) * BINS + b;
        float s = 0.0f;
        #pragma unroll
        for (int k = 0; k < BPS; k++) s += p[k * BINS];
        s_hist[tid] = s;
    }
    __syncthreads();

    {
        const int j    = tid & 127;
        const int half = tid >> 7;
        const int c0   = half * 96;
        float acc = 0.0f;
        #pragma unroll 16
        for (int c = c0; c < c0 + 96; c++)
            acc = fmaf(s_hist[c], s_w1[c * 128 + j], acc);
        s_p1[half * 128 + j] = acc;
    }
    __syncthreads();
    if (tid < 128)
        s_h1[tid] = fmaxf(s_p1[tid] + s_p1[128 + tid] + params[P_B1 + tid], 0.0f);
    __syncthreads();

    if (tid < 128) {
        const int q = tid >> 5;
        const int k = tid & 31;
        float a = 0.0f;
        #pragma unroll
        for (int c = q * 32; c < q * 32 + 32; c++)
            a = fmaf(s_h1[c], s_w2[c * 32 + k], a);
        s_l2[tid] = a;
    }
    __syncthreads();

    if (tid < 32) {
        float a = params[P_B2 + tid] + params[P_G]
                + s_l2[tid] + s_l2[32 + tid] + s_l2[64 + tid] + s_l2[96 + tid];
        out[n * 32 + tid] = 1.0f / (1.0f + expf(-a));
    }
}

extern "C" void kernel_launch(void* const* d_in, const int* in_sizes, int n_in,
                              void* d_out, int out_size) {
    const float* img    = (const float*)d_in[0];
    const float* params = (const float*)d_in[1];
    float* out          = (float*)d_out;

    static bool attr_set = false;
    if (!attr_set) {
        cudaFuncSetAttribute(hist_kernel, cudaFuncAttributeMaxDynamicSharedMemorySize, HSMEM_BYTES);
        cudaFuncSetAttribute(mlp_kernel,  cudaFuncAttributeMaxDynamicSharedMemorySize, MLP_SMEM_BYTES);
        attr_set = true;
    }

    hist_kernel<<<NBLOCKS, HTHREADS, HSMEM_BYTES>>>(img);

    cudaLaunchConfig_t cfg = {};
    cfg.gridDim  = dim3(MLP_BLOCKS, 1, 1);
    cfg.blockDim = dim3(MLP_THREADS, 1, 1);
    cfg.dynamicSmemBytes = MLP_SMEM_BYTES;
    cudaLaunchAttribute attrs[1];
    attrs[0].id = cudaLaunchAttributeProgrammaticStreamSerialization;
    attrs[0].val.programmaticStreamSerializationAllowed = 1;
    cfg.attrs = attrs;
    cfg.numAttrs = 1;
    cudaLaunchKernelEx(&cfg, mlp_kernel, params, out);
}